// round 6
// baseline (speedup 1.0000x reference)
#include <cuda_runtime.h>
#include <cstdint>

#define NN 100000
#define NE 1600000
#define D  128
#define NG 2048
#define NL 3

// ---------------- scratch (device globals: alloc-free) ----------------
__device__ int   g_degi [NN];
__device__ float g_dinv [NN];
__device__ int   g_fill [NN];
__device__ int   g_off  [NN + 1];
__device__ int   g_csrc [NE];       // CSR: src per slot
__device__ float g_cnrm [NE];       // CSR: norm per slot
__device__ int   g_start[NG + 1];   // graph boundaries in sorted batch
__device__ float g_t    [NN * D];   // h @ W
__device__ float g_agg  [NN * D];   // aggregated (pre bias/relu)

__device__ __forceinline__ void fma4(float4& a, float s, const float4& c) {
    a.x = fmaf(s, c.x, a.x);
    a.y = fmaf(s, c.y, a.y);
    a.z = fmaf(s, c.z, a.z);
    a.w = fmaf(s, c.w, a.w);
}

// ---------------- init ---------------------------------------------------
__global__ void k_init() {
    int i = blockIdx.x * blockDim.x + threadIdx.x;
    if (i < NN) { g_degi[i] = 1; g_fill[i] = 0; }   // 1 = self loop
}

// ---------------- in-degree over edge dst ---------------------------------
__global__ void k_deg(const int* __restrict__ ei) {
    int e = blockIdx.x * blockDim.x + threadIdx.x;
    if (e < NE) atomicAdd(&g_degi[ei[NE + e]], 1);
}

__global__ void k_dinv() {
    int i = blockIdx.x * blockDim.x + threadIdx.x;
    if (i < NN) g_dinv[i] = rsqrtf((float)g_degi[i]);
}

// ---------------- exclusive scan of per-node edge counts -> g_off ---------
__global__ void k_scan() {
    __shared__ int wsum[32];
    __shared__ int s_carry;
    int tid = threadIdx.x;            // 1024 threads, single block
    int lane = tid & 31, w = tid >> 5;
    if (tid == 0) s_carry = 0;
    __syncthreads();
    for (int base = 0; base < NN; base += 1024) {
        int i = base + tid;
        int val = (i < NN) ? (g_degi[i] - 1) : 0;
        int incl = val;
        #pragma unroll
        for (int o = 1; o < 32; o <<= 1) {
            int t = __shfl_up_sync(0xffffffffu, incl, o);
            if (lane >= o) incl += t;
        }
        if (lane == 31) wsum[w] = incl;
        __syncthreads();
        if (w == 0) {
            int s = wsum[lane];
            #pragma unroll
            for (int o = 1; o < 32; o <<= 1) {
                int t = __shfl_up_sync(0xffffffffu, s, o);
                if (lane >= o) s += t;
            }
            wsum[lane] = s;
        }
        __syncthreads();
        int blockIncl = incl + (w ? wsum[w - 1] : 0);
        int excl = s_carry + blockIncl - val;
        if (i < NN) g_off[i] = excl;
        __syncthreads();
        if (tid == 1023) s_carry += blockIncl;
        __syncthreads();
    }
    if (tid == 0) g_off[NN] = s_carry;
}

// ---------------- CSR fill -------------------------------------------------
__global__ void k_fill(const int* __restrict__ ei) {
    int e = blockIdx.x * blockDim.x + threadIdx.x;
    if (e >= NE) return;
    int s = ei[e];
    int d = ei[NE + e];
    int pos = g_off[d] + atomicAdd(&g_fill[d], 1);
    g_csrc[pos] = s;
    g_cnrm[pos] = g_dinv[s] * g_dinv[d];
}

// ---------------- graph boundaries from sorted batch -----------------------
__global__ void k_bnd(const int* __restrict__ batch) {
    int i = blockIdx.x * blockDim.x + threadIdx.x;
    if (i >= NN) return;
    int b1 = batch[i];
    int b0 = (i == 0) ? -1 : batch[i - 1];
    for (int g = b0 + 1; g <= b1; g++) g_start[g] = i;
    if (i == NN - 1)
        for (int g = b1 + 1; g <= NG; g++) g_start[g] = NN;
}

// ---------------- GEMM: t = prologue(in) @ W[l] -----------------------------
// prologue (layers 1,2): in = relu(g_agg + b[l-1]); layer 0: in = x raw.
// 256 threads/block, 64 input rows staged in 32KB static smem.
// W read via __ldg (block-uniform addresses -> L1 resident).
__global__ void __launch_bounds__(256)
k_gemm(const float* __restrict__ x0, const float* __restrict__ W,
       const float* __restrict__ bias, int layer) {
    __shared__ float sIn[64 * D];     // 32 KB
    float4* sIn4 = (float4*)sIn;

    const float* in = (layer == 0) ? x0 : g_agg;
    int tid = threadIdx.x;
    int rowBase = blockIdx.x * 64;

    const float4* in4 = (const float4*)in;
    #pragma unroll
    for (int i = 0; i < 8; i++) {
        int idx = tid + 256 * i;        // 0..2047
        int r   = idx >> 5;
        int gr  = rowBase + r;
        float4 v = make_float4(0.f, 0.f, 0.f, 0.f);
        if (gr < NN) {
            v = in4[gr * 32 + (idx & 31)];
            if (layer != 0) {
                float4 bb = __ldg(&((const float4*)bias)[idx & 31]);
                v.x = fmaxf(v.x + bb.x, 0.f);
                v.y = fmaxf(v.y + bb.y, 0.f);
                v.z = fmaxf(v.z + bb.z, 0.f);
                v.w = fmaxf(v.w + bb.w, 0.f);
            }
        }
        sIn4[idx] = v;
    }
    __syncthreads();

    int lane = tid & 31;
    int wrp  = tid >> 5;
    int r0   = wrp * 8;

    float4 acc[8];
    #pragma unroll
    for (int i = 0; i < 8; i++) acc[i] = make_float4(0.f, 0.f, 0.f, 0.f);

    const float4* W4 = (const float4*)W;   // W[k][n] row-major, 32 float4/row
    for (int k = 0; k < D; k += 4) {
        float4 wv0 = __ldg(&W4[(k + 0) * 32 + lane]);
        float4 wv1 = __ldg(&W4[(k + 1) * 32 + lane]);
        float4 wv2 = __ldg(&W4[(k + 2) * 32 + lane]);
        float4 wv3 = __ldg(&W4[(k + 3) * 32 + lane]);
        int kq = k >> 2;
        #pragma unroll
        for (int i = 0; i < 8; i++) {
            float4 iv = sIn4[(r0 + i) * 32 + kq];
            fma4(acc[i], iv.x, wv0);
            fma4(acc[i], iv.y, wv1);
            fma4(acc[i], iv.z, wv2);
            fma4(acc[i], iv.w, wv3);
        }
    }

    float4* out4 = (float4*)g_t;
    #pragma unroll
    for (int i = 0; i < 8; i++) {
        int gr = rowBase + r0 + i;
        if (gr < NN) out4[gr * 32 + lane] = acc[i];
    }
}

// ---------------- gather: agg[d] = dinv[d]^2 * t[d] + sum norm * t[src] ----
// One warp per node; lane j owns float4 feature chunk j.
__global__ void __launch_bounds__(256)
k_gather() {
    int gw = (blockIdx.x * blockDim.x + threadIdx.x) >> 5;
    if (gw >= NN) return;
    int j = threadIdx.x & 31;
    int d = gw;
    const float4* t4 = (const float4*)g_t;

    float dv = g_dinv[d];
    float s2 = dv * dv;
    float4 acc = t4[d * 32 + j];
    acc.x *= s2; acc.y *= s2; acc.z *= s2; acc.w *= s2;

    int e   = g_off[d];
    int end = g_off[d + 1];
    for (; e + 2 <= end; e += 2) {
        int   s0 = g_csrc[e];
        int   s1 = g_csrc[e + 1];
        float n0 = g_cnrm[e];
        float n1 = g_cnrm[e + 1];
        float4 v0 = t4[s0 * 32 + j];
        float4 v1 = t4[s1 * 32 + j];
        fma4(acc, n0, v0);
        fma4(acc, n1, v1);
    }
    if (e < end) {
        int   s0 = g_csrc[e];
        float n0 = g_cnrm[e];
        float4 v0 = t4[s0 * 32 + j];
        fma4(acc, n0, v0);
    }
    ((float4*)g_agg)[d * 32 + j] = acc;
}

// ---------------- fused pool + final linear --------------------------------
// One block (128 threads) per graph: mean(relu(agg+b2)) . lin_w + lin_b
__global__ void __launch_bounds__(128)
k_poolout(const float* __restrict__ bias, const float* __restrict__ lin_w,
          const float* __restrict__ lin_b, float* __restrict__ out) {
    int g = blockIdx.x;
    int j = threadIdx.x;          // feature index
    int beg = g_start[g];
    int end = g_start[g + 1];
    float bb = bias[j];
    float acc = 0.0f;
    for (int r = beg; r < end; r++)
        acc += fmaxf(g_agg[r * D + j] + bb, 0.0f);

    float p = acc * lin_w[j];
    #pragma unroll
    for (int o = 16; o > 0; o >>= 1) p += __shfl_xor_sync(0xffffffffu, p, o);

    __shared__ float ws[4];
    if ((j & 31) == 0) ws[j >> 5] = p;
    __syncthreads();
    if (j == 0) {
        float tot = ws[0] + ws[1] + ws[2] + ws[3];
        float cnt = (float)(end - beg);
        float inv = 1.0f / fmaxf(cnt, 1.0f);
        out[g] = tot * inv + lin_b[0];
    }
}

// ---------------- launch -----------------------------------------------------
extern "C" void kernel_launch(void* const* d_in, const int* in_sizes, int n_in,
                              void* d_out, int out_size) {
    // Identify inputs BY ELEMENT COUNT (all sizes unique).
    // Harness dtypes: float32 / int32 / bf16 — int64 tensors arrive as int32.
    const float *x = 0, *W = 0, *b = 0, *lin_w = 0, *lin_b = 0;
    const int   *ei = 0, *batch = 0;
    for (int i = 0; i < n_in; i++) {
        switch (in_sizes[i]) {
            case NN * D:      x     = (const float*)d_in[i]; break;  // 12.8M
            case 2 * NE:      ei    = (const int*)d_in[i];   break;  // 3.2M
            case NN:          batch = (const int*)d_in[i];   break;  // 100k
            case NL * D * D:  W     = (const float*)d_in[i]; break;  // 49152
            case NL * D:      b     = (const float*)d_in[i]; break;  // 384
            case D:           lin_w = (const float*)d_in[i]; break;  // 128
            case 1:           lin_b = (const float*)d_in[i]; break;  // 1
        }
    }
    float* out = (float*)d_out;

    const int T = 256;
    k_init<<<(NN + T - 1) / T, T>>>();
    k_deg <<<(NE + T - 1) / T, T>>>(ei);
    k_dinv<<<(NN + T - 1) / T, T>>>();
    k_scan<<<1, 1024>>>();
    k_fill<<<(NE + T - 1) / T, T>>>(ei);
    k_bnd <<<(NN + T - 1) / T, T>>>(batch);

    int gemmGrid   = (NN + 63) / 64;
    int gatherGrid = (NN * 32 + T - 1) / T;   // one warp per node

    for (int l = 0; l < NL; l++) {
        const float* Wl = W + (size_t)l * D * D;
        const float* bl = (l == 0) ? b : (b + (size_t)(l - 1) * D);
        k_gemm  <<<gemmGrid, T>>>(x, Wl, bl, l);
        k_gather<<<gatherGrid, T>>>();
    }

    k_poolout<<<NG, 128>>>(b + 2 * D, lin_w, lin_b, out);
}

// round 7
// speedup vs baseline: 1.1044x; 1.1044x over previous
#include <cuda_runtime.h>
#include <cstdint>

#define NN 100000
#define NE 1600000
#define D  128
#define NG 2048
#define NL 3
#define SCAN_NBLK ((NN + 1023) / 1024)   // 98

// ---------------- scratch (device globals: alloc-free) ----------------
__device__ int   g_degi [NN];
__device__ float g_dinv [NN];
__device__ int   g_fill [NN];
__device__ int   g_off  [NN + 1];
__device__ int   g_part [SCAN_NBLK];
__device__ int   g_csrc [NE];       // CSR: src per slot
__device__ float g_cnrm [NE];       // CSR: norm per slot
__device__ int   g_start[NG + 1];   // graph boundaries in sorted batch
__device__ float g_t    [NN * D];   // h @ W
__device__ float g_agg  [NN * D];   // aggregated (pre bias/relu)

__device__ __forceinline__ void fma4(float4& a, float s, const float4& c) {
    a.x = fmaf(s, c.x, a.x);
    a.y = fmaf(s, c.y, a.y);
    a.z = fmaf(s, c.z, a.z);
    a.w = fmaf(s, c.w, a.w);
}

// ---------------- init ---------------------------------------------------
__global__ void k_init() {
    int i = blockIdx.x * blockDim.x + threadIdx.x;
    if (i < NN) { g_degi[i] = 1; g_fill[i] = 0; }   // 1 = self loop
}

// ---------------- in-degree over edge dst ---------------------------------
__global__ void k_deg(const int* __restrict__ ei) {
    int e = blockIdx.x * blockDim.x + threadIdx.x;
    if (e < NE) atomicAdd(&g_degi[ei[NE + e]], 1);
}

// ---------------- 3-pass multi-block exclusive scan of (deg-1) ------------
// Pass A: per-block sums
__global__ void __launch_bounds__(1024)
k_scanA() {
    __shared__ int wsum[32];
    int tid = threadIdx.x, lane = tid & 31, w = tid >> 5;
    int i = blockIdx.x * 1024 + tid;
    int s = (i < NN) ? (g_degi[i] - 1) : 0;
    #pragma unroll
    for (int o = 16; o > 0; o >>= 1) s += __shfl_xor_sync(0xffffffffu, s, o);
    if (lane == 0) wsum[w] = s;
    __syncthreads();
    if (w == 0) {
        int t = wsum[lane];
        #pragma unroll
        for (int o = 16; o > 0; o >>= 1) t += __shfl_xor_sync(0xffffffffu, t, o);
        if (lane == 0) g_part[blockIdx.x] = t;
    }
}

// Pass B: single warp exclusive-scans the 98 partials
__global__ void k_scanB() {
    int lane = threadIdx.x;
    int carry = 0;
    for (int base = 0; base < SCAN_NBLK; base += 32) {
        int i = base + lane;
        int v = (i < SCAN_NBLK) ? g_part[i] : 0;
        int incl = v;
        #pragma unroll
        for (int o = 1; o < 32; o <<= 1) {
            int t = __shfl_up_sync(0xffffffffu, incl, o);
            if (lane >= o) incl += t;
        }
        if (i < SCAN_NBLK) g_part[i] = carry + incl - v;
        carry += __shfl_sync(0xffffffffu, incl, 31);
    }
}

// Pass C: per-block scan + base add; also computes dinv and g_off[NN]
__global__ void __launch_bounds__(1024)
k_scanC() {
    __shared__ int wsum[32];
    int tid = threadIdx.x, lane = tid & 31, w = tid >> 5;
    int i = blockIdx.x * 1024 + tid;
    int val = (i < NN) ? (g_degi[i] - 1) : 0;
    int incl = val;
    #pragma unroll
    for (int o = 1; o < 32; o <<= 1) {
        int t = __shfl_up_sync(0xffffffffu, incl, o);
        if (lane >= o) incl += t;
    }
    if (lane == 31) wsum[w] = incl;
    __syncthreads();
    if (w == 0) {
        int s = wsum[lane];
        #pragma unroll
        for (int o = 1; o < 32; o <<= 1) {
            int t = __shfl_up_sync(0xffffffffu, s, o);
            if (lane >= o) s += t;
        }
        wsum[lane] = s;
    }
    __syncthreads();
    if (i < NN) {
        g_off[i] = g_part[blockIdx.x] + (w ? wsum[w - 1] : 0) + incl - val;
        g_dinv[i] = rsqrtf((float)g_degi[i]);
    }
    if (i == 0) g_off[NN] = NE;   // total edges (deg-1 sums to NE)
}

// ---------------- CSR fill -------------------------------------------------
__global__ void k_fill(const int* __restrict__ ei) {
    int e = blockIdx.x * blockDim.x + threadIdx.x;
    if (e >= NE) return;
    int s = ei[e];
    int d = ei[NE + e];
    int pos = g_off[d] + atomicAdd(&g_fill[d], 1);
    g_csrc[pos] = s;
    g_cnrm[pos] = g_dinv[s] * g_dinv[d];
}

// ---------------- graph boundaries from sorted batch -----------------------
__global__ void k_bnd(const int* __restrict__ batch) {
    int i = blockIdx.x * blockDim.x + threadIdx.x;
    if (i >= NN) return;
    int b1 = batch[i];
    int b0 = (i == 0) ? -1 : batch[i - 1];
    for (int g = b0 + 1; g <= b1; g++) g_start[g] = i;
    if (i == NN - 1)
        for (int g = b1 + 1; g <= NG; g++) g_start[g] = NN;
}

// ---------------- GEMM: t = prologue(in) @ W[l] -----------------------------
// prologue (layers 1,2): in = relu(g_agg + b[l-1]); layer 0: in = x raw.
__global__ void __launch_bounds__(256)
k_gemm(const float* __restrict__ x0, const float* __restrict__ W,
       const float* __restrict__ bias, int layer) {
    __shared__ float sIn[64 * D];     // 32 KB
    float4* sIn4 = (float4*)sIn;

    const float* in = (layer == 0) ? x0 : g_agg;
    int tid = threadIdx.x;
    int rowBase = blockIdx.x * 64;

    const float4* in4 = (const float4*)in;
    #pragma unroll
    for (int i = 0; i < 8; i++) {
        int idx = tid + 256 * i;        // 0..2047
        int r   = idx >> 5;
        int gr  = rowBase + r;
        float4 v = make_float4(0.f, 0.f, 0.f, 0.f);
        if (gr < NN) {
            v = in4[gr * 32 + (idx & 31)];
            if (layer != 0) {
                float4 bb = __ldg(&((const float4*)bias)[idx & 31]);
                v.x = fmaxf(v.x + bb.x, 0.f);
                v.y = fmaxf(v.y + bb.y, 0.f);
                v.z = fmaxf(v.z + bb.z, 0.f);
                v.w = fmaxf(v.w + bb.w, 0.f);
            }
        }
        sIn4[idx] = v;
    }
    __syncthreads();

    int lane = tid & 31;
    int wrp  = tid >> 5;
    int r0   = wrp * 8;

    float4 acc[8];
    #pragma unroll
    for (int i = 0; i < 8; i++) acc[i] = make_float4(0.f, 0.f, 0.f, 0.f);

    const float4* W4 = (const float4*)W;   // W[k][n] row-major, 32 float4/row
    for (int k = 0; k < D; k += 4) {
        float4 wv0 = __ldg(&W4[(k + 0) * 32 + lane]);
        float4 wv1 = __ldg(&W4[(k + 1) * 32 + lane]);
        float4 wv2 = __ldg(&W4[(k + 2) * 32 + lane]);
        float4 wv3 = __ldg(&W4[(k + 3) * 32 + lane]);
        int kq = k >> 2;
        #pragma unroll
        for (int i = 0; i < 8; i++) {
            float4 iv = sIn4[(r0 + i) * 32 + kq];
            fma4(acc[i], iv.x, wv0);
            fma4(acc[i], iv.y, wv1);
            fma4(acc[i], iv.z, wv2);
            fma4(acc[i], iv.w, wv3);
        }
    }

    float4* out4 = (float4*)g_t;
    #pragma unroll
    for (int i = 0; i < 8; i++) {
        int gr = rowBase + r0 + i;
        if (gr < NN) out4[gr * 32 + lane] = acc[i];
    }
}

// ---------------- gather: agg[d] = dinv[d]^2 * t[d] + sum norm * t[src] ----
__global__ void __launch_bounds__(256)
k_gather() {
    int gw = (blockIdx.x * blockDim.x + threadIdx.x) >> 5;
    if (gw >= NN) return;
    int j = threadIdx.x & 31;
    int d = gw;
    const float4* t4 = (const float4*)g_t;

    float dv = g_dinv[d];
    float s2 = dv * dv;
    float4 acc = t4[d * 32 + j];
    acc.x *= s2; acc.y *= s2; acc.z *= s2; acc.w *= s2;

    int e   = g_off[d];
    int end = g_off[d + 1];
    for (; e + 2 <= end; e += 2) {
        int   s0 = __ldg(&g_csrc[e]);
        int   s1 = __ldg(&g_csrc[e + 1]);
        float n0 = __ldg(&g_cnrm[e]);
        float n1 = __ldg(&g_cnrm[e + 1]);
        float4 v0 = t4[s0 * 32 + j];
        float4 v1 = t4[s1 * 32 + j];
        fma4(acc, n0, v0);
        fma4(acc, n1, v1);
    }
    if (e < end) {
        int   s0 = __ldg(&g_csrc[e]);
        float n0 = __ldg(&g_cnrm[e]);
        float4 v0 = t4[s0 * 32 + j];
        fma4(acc, n0, v0);
    }
    ((float4*)g_agg)[d * 32 + j] = acc;
}

// ---------------- fused pool + final linear --------------------------------
__global__ void __launch_bounds__(128)
k_poolout(const float* __restrict__ bias, const float* __restrict__ lin_w,
          const float* __restrict__ lin_b, float* __restrict__ out) {
    int g = blockIdx.x;
    int j = threadIdx.x;          // feature index
    int beg = g_start[g];
    int end = g_start[g + 1];
    float bb = bias[j];
    float acc = 0.0f;
    for (int r = beg; r < end; r++)
        acc += fmaxf(g_agg[r * D + j] + bb, 0.0f);

    float p = acc * lin_w[j];
    #pragma unroll
    for (int o = 16; o > 0; o >>= 1) p += __shfl_xor_sync(0xffffffffu, p, o);

    __shared__ float ws[4];
    if ((j & 31) == 0) ws[j >> 5] = p;
    __syncthreads();
    if (j == 0) {
        float tot = ws[0] + ws[1] + ws[2] + ws[3];
        float cnt = (float)(end - beg);
        float inv = 1.0f / fmaxf(cnt, 1.0f);
        out[g] = tot * inv + lin_b[0];
    }
}

// ---------------- launch -----------------------------------------------------
extern "C" void kernel_launch(void* const* d_in, const int* in_sizes, int n_in,
                              void* d_out, int out_size) {
    // Identify inputs BY ELEMENT COUNT (all sizes unique); int64 arrives as int32.
    const float *x = 0, *W = 0, *b = 0, *lin_w = 0, *lin_b = 0;
    const int   *ei = 0, *batch = 0;
    for (int i = 0; i < n_in; i++) {
        switch (in_sizes[i]) {
            case NN * D:      x     = (const float*)d_in[i]; break;  // 12.8M
            case 2 * NE:      ei    = (const int*)d_in[i];   break;  // 3.2M
            case NN:          batch = (const int*)d_in[i];   break;  // 100k
            case NL * D * D:  W     = (const float*)d_in[i]; break;  // 49152
            case NL * D:      b     = (const float*)d_in[i]; break;  // 384
            case D:           lin_w = (const float*)d_in[i]; break;  // 128
            case 1:           lin_b = (const float*)d_in[i]; break;  // 1
        }
    }
    float* out = (float*)d_out;

    const int T = 256;
    k_init <<<(NN + T - 1) / T, T>>>();
    k_deg  <<<(NE + T - 1) / T, T>>>(ei);
    k_scanA<<<SCAN_NBLK, 1024>>>();
    k_scanB<<<1, 32>>>();
    k_scanC<<<SCAN_NBLK, 1024>>>();
    k_fill <<<(NE + T - 1) / T, T>>>(ei);
    k_bnd  <<<(NN + T - 1) / T, T>>>(batch);

    int gemmGrid   = (NN + 63) / 64;
    int gatherGrid = (NN * 32 + T - 1) / T;   // one warp per node

    for (int l = 0; l < NL; l++) {
        const float* Wl = W + (size_t)l * D * D;
        const float* bl = (l == 0) ? b : (b + (size_t)(l - 1) * D);
        k_gemm  <<<gemmGrid, T>>>(x, Wl, bl, l);
        k_gather<<<gatherGrid, T>>>();
    }

    k_poolout<<<NG, 128>>>(b + 2 * D, lin_w, lin_b, out);
}

// round 8
// speedup vs baseline: 1.4924x; 1.3513x over previous
#include <cuda_runtime.h>
#include <cstdint>

#define NN 100000
#define NE 1600000
#define D  128
#define NG 2048
#define NL 3
#define SCAN_NBLK ((NN + 1023) / 1024)   // 98

// ---------------- scratch (device globals: alloc-free) ----------------
__device__ int      g_degi [NN];
__device__ float    g_dinv [NN];
__device__ int      g_fill [NN];
__device__ int      g_off  [NN + 1];
__device__ int      g_part [SCAN_NBLK];
__device__ int      g_csrc [NE];
__device__ float    g_cnrm [NE];
__device__ int      g_start[NG + 1];
__device__ float    g_t    [NN * D];
__device__ float    g_agg  [NN * D];
// W in tf32, fragment-ordered: [layer][kstep 16][ntile 16][lane 32][2]
__device__ uint32_t g_wf   [NL * 16 * 16 * 64];

__device__ __forceinline__ void fma4(float4& a, float s, const float4& c) {
    a.x = fmaf(s, c.x, a.x);
    a.y = fmaf(s, c.y, a.y);
    a.z = fmaf(s, c.z, a.z);
    a.w = fmaf(s, c.w, a.w);
}

__device__ __forceinline__ uint32_t f2tf32(float f) {
    uint32_t r;
    asm("cvt.rna.tf32.f32 %0, %1;" : "=r"(r) : "f"(f));
    return r;
}

// ---------------- init ------------------------------------------------
__global__ void k_init() {
    int i = blockIdx.x * blockDim.x + threadIdx.x;
    if (i < NN) { g_degi[i] = 1; g_fill[i] = 0; }
}

__global__ void k_deg(const int* __restrict__ ei) {
    int e = blockIdx.x * blockDim.x + threadIdx.x;
    if (e < NE) atomicAdd(&g_degi[ei[NE + e]], 1);
}

// ---------------- 3-pass exclusive scan of (deg-1) ---------------------
__global__ void __launch_bounds__(1024)
k_scanA() {
    __shared__ int wsum[32];
    int tid = threadIdx.x, lane = tid & 31, w = tid >> 5;
    int i = blockIdx.x * 1024 + tid;
    int s = (i < NN) ? (g_degi[i] - 1) : 0;
    #pragma unroll
    for (int o = 16; o > 0; o >>= 1) s += __shfl_xor_sync(0xffffffffu, s, o);
    if (lane == 0) wsum[w] = s;
    __syncthreads();
    if (w == 0) {
        int t = wsum[lane];
        #pragma unroll
        for (int o = 16; o > 0; o >>= 1) t += __shfl_xor_sync(0xffffffffu, t, o);
        if (lane == 0) g_part[blockIdx.x] = t;
    }
}

__global__ void k_scanB() {
    int lane = threadIdx.x;
    int carry = 0;
    for (int base = 0; base < SCAN_NBLK; base += 32) {
        int i = base + lane;
        int v = (i < SCAN_NBLK) ? g_part[i] : 0;
        int incl = v;
        #pragma unroll
        for (int o = 1; o < 32; o <<= 1) {
            int t = __shfl_up_sync(0xffffffffu, incl, o);
            if (lane >= o) incl += t;
        }
        if (i < SCAN_NBLK) g_part[i] = carry + incl - v;
        carry += __shfl_sync(0xffffffffu, incl, 31);
    }
}

__global__ void __launch_bounds__(1024)
k_scanC() {
    __shared__ int wsum[32];
    int tid = threadIdx.x, lane = tid & 31, w = tid >> 5;
    int i = blockIdx.x * 1024 + tid;
    int val = (i < NN) ? (g_degi[i] - 1) : 0;
    int incl = val;
    #pragma unroll
    for (int o = 1; o < 32; o <<= 1) {
        int t = __shfl_up_sync(0xffffffffu, incl, o);
        if (lane >= o) incl += t;
    }
    if (lane == 31) wsum[w] = incl;
    __syncthreads();
    if (w == 0) {
        int s = wsum[lane];
        #pragma unroll
        for (int o = 1; o < 32; o <<= 1) {
            int t = __shfl_up_sync(0xffffffffu, s, o);
            if (lane >= o) s += t;
        }
        wsum[lane] = s;
    }
    __syncthreads();
    if (i < NN) {
        g_off[i] = g_part[blockIdx.x] + (w ? wsum[w - 1] : 0) + incl - val;
        g_dinv[i] = rsqrtf((float)g_degi[i]);
    }
    if (i == 0) g_off[NN] = NE;
}

// ---------------- CSR fill ---------------------------------------------
__global__ void k_fill(const int* __restrict__ ei) {
    int e = blockIdx.x * blockDim.x + threadIdx.x;
    if (e >= NE) return;
    int s = ei[e];
    int d = ei[NE + e];
    int pos = g_off[d] + atomicAdd(&g_fill[d], 1);
    g_csrc[pos] = s;
    g_cnrm[pos] = g_dinv[s] * g_dinv[d];
}

// ---------------- graph boundaries --------------------------------------
__global__ void k_bnd(const int* __restrict__ batch) {
    int i = blockIdx.x * blockDim.x + threadIdx.x;
    if (i >= NN) return;
    int b1 = batch[i];
    int b0 = (i == 0) ? -1 : batch[i - 1];
    for (int g = b0 + 1; g <= b1; g++) g_start[g] = i;
    if (i == NN - 1)
        for (int g = b1 + 1; g <= NG; g++) g_start[g] = NN;
}

// ---------------- W -> tf32 fragment layout ------------------------------
// frag index: (((l*16 + s)*16 + j)*32 + lane)*2 + {0,1}
// b0 = W[l][8s + t][8j + g], b1 = W[l][8s + t + 4][8j + g]; g=lane>>2, t=lane&3
__global__ void k_wprep(const float* __restrict__ W) {
    int tid = blockIdx.x * blockDim.x + threadIdx.x;    // 0 .. 24575
    if (tid >= NL * 16 * 16 * 32) return;
    int lane = tid & 31;
    int j    = (tid >> 5) & 15;
    int s    = (tid >> 9) & 15;
    int l    = tid >> 13;
    int g = lane >> 2, t = lane & 3;
    const float* Wl = W + l * D * D;
    float w0 = Wl[(8 * s + t) * D + 8 * j + g];
    float w1 = Wl[(8 * s + t + 4) * D + 8 * j + g];
    g_wf[tid * 2 + 0] = f2tf32(w0);
    g_wf[tid * 2 + 1] = f2tf32(w1);
}

// ---------------- TF32 tensor-core GEMM: t = prologue(in) @ W[l] --------
// Block 256 thr = 8 warps; warp w owns rows [blk*128 + 16w, +16), all N=128.
__global__ void __launch_bounds__(256)
k_gemm(const float* __restrict__ x0, const float* __restrict__ bias, int layer) {
    const float* in = (layer == 0) ? x0 : g_agg;
    int lane = threadIdx.x & 31;
    int w    = threadIdx.x >> 5;
    int g = lane >> 2, t = lane & 3;
    int m0 = blockIdx.x * 128 + w * 16;
    int row0 = m0 + g;
    int row1 = m0 + g + 8;
    int r0c = (row0 < NN) ? row0 : (NN - 1);   // clamp loads; stores guarded
    int r1c = (row1 < NN) ? row1 : (NN - 1);

    float acc[16][4];
    #pragma unroll
    for (int j = 0; j < 16; j++)
        { acc[j][0] = 0.f; acc[j][1] = 0.f; acc[j][2] = 0.f; acc[j][3] = 0.f; }

    const uint32_t* wf = g_wf + (layer * 16) * 16 * 64 + lane * 2;

    #pragma unroll
    for (int s = 0; s < 16; s++) {
        int k0 = 8 * s;
        float a0f = __ldg(&in[r0c * D + k0 + t]);
        float a1f = __ldg(&in[r1c * D + k0 + t]);
        float a2f = __ldg(&in[r0c * D + k0 + t + 4]);
        float a3f = __ldg(&in[r1c * D + k0 + t + 4]);
        if (layer != 0) {
            float b0 = __ldg(&bias[k0 + t]);
            float b1 = __ldg(&bias[k0 + t + 4]);
            a0f = fmaxf(a0f + b0, 0.f);
            a1f = fmaxf(a1f + b0, 0.f);
            a2f = fmaxf(a2f + b1, 0.f);
            a3f = fmaxf(a3f + b1, 0.f);
        }
        uint32_t a0 = f2tf32(a0f), a1 = f2tf32(a1f);
        uint32_t a2 = f2tf32(a2f), a3 = f2tf32(a3f);

        const uint32_t* wfs = wf + s * 16 * 64;
        #pragma unroll
        for (int j = 0; j < 16; j++) {
            uint2 bv = *(const uint2*)(wfs + j * 64);
            asm volatile(
                "mma.sync.aligned.m16n8k8.row.col.f32.tf32.tf32.f32 "
                "{%0,%1,%2,%3}, {%4,%5,%6,%7}, {%8,%9}, {%0,%1,%2,%3};"
                : "+f"(acc[j][0]), "+f"(acc[j][1]), "+f"(acc[j][2]), "+f"(acc[j][3])
                : "r"(a0), "r"(a1), "r"(a2), "r"(a3), "r"(bv.x), "r"(bv.y));
        }
    }

    // epilogue: c0,c1 -> (row0, 8j+2t..+1); c2,c3 -> (row1, same cols)
    #pragma unroll
    for (int j = 0; j < 16; j++) {
        int c = 8 * j + 2 * t;
        if (row0 < NN)
            *(float2*)&g_t[row0 * D + c] = make_float2(acc[j][0], acc[j][1]);
        if (row1 < NN)
            *(float2*)&g_t[row1 * D + c] = make_float2(acc[j][2], acc[j][3]);
    }
}

// ---------------- gather: agg[d] = dinv^2 * t[d] + sum norm * t[src] ----
__global__ void __launch_bounds__(256)
k_gather() {
    int gw = (blockIdx.x * blockDim.x + threadIdx.x) >> 5;
    if (gw >= NN) return;
    int j = threadIdx.x & 31;
    int d = gw;
    const float4* t4 = (const float4*)g_t;

    float dv = g_dinv[d];
    float s2 = dv * dv;
    float4 acc = t4[d * 32 + j];
    acc.x *= s2; acc.y *= s2; acc.z *= s2; acc.w *= s2;

    int e   = g_off[d];
    int end = g_off[d + 1];
    for (; e + 2 <= end; e += 2) {
        int   s0 = __ldg(&g_csrc[e]);
        int   s1 = __ldg(&g_csrc[e + 1]);
        float n0 = __ldg(&g_cnrm[e]);
        float n1 = __ldg(&g_cnrm[e + 1]);
        float4 v0 = t4[s0 * 32 + j];
        float4 v1 = t4[s1 * 32 + j];
        fma4(acc, n0, v0);
        fma4(acc, n1, v1);
    }
    if (e < end) {
        int   s0 = __ldg(&g_csrc[e]);
        float n0 = __ldg(&g_cnrm[e]);
        float4 v0 = t4[s0 * 32 + j];
        fma4(acc, n0, v0);
    }
    ((float4*)g_agg)[d * 32 + j] = acc;
}

// ---------------- fused pool + final linear ------------------------------
__global__ void __launch_bounds__(128)
k_poolout(const float* __restrict__ bias, const float* __restrict__ lin_w,
          const float* __restrict__ lin_b, float* __restrict__ out) {
    int g = blockIdx.x;
    int j = threadIdx.x;
    int beg = g_start[g];
    int end = g_start[g + 1];
    float bb = bias[j];
    float acc = 0.0f;
    for (int r = beg; r < end; r++)
        acc += fmaxf(g_agg[r * D + j] + bb, 0.0f);

    float p = acc * lin_w[j];
    #pragma unroll
    for (int o = 16; o > 0; o >>= 1) p += __shfl_xor_sync(0xffffffffu, p, o);

    __shared__ float ws[4];
    if ((j & 31) == 0) ws[j >> 5] = p;
    __syncthreads();
    if (j == 0) {
        float tot = ws[0] + ws[1] + ws[2] + ws[3];
        float cnt = (float)(end - beg);
        float inv = 1.0f / fmaxf(cnt, 1.0f);
        out[g] = tot * inv + lin_b[0];
    }
}

// ---------------- launch --------------------------------------------------
extern "C" void kernel_launch(void* const* d_in, const int* in_sizes, int n_in,
                              void* d_out, int out_size) {
    const float *x = 0, *W = 0, *b = 0, *lin_w = 0, *lin_b = 0;
    const int   *ei = 0, *batch = 0;
    for (int i = 0; i < n_in; i++) {
        switch (in_sizes[i]) {
            case NN * D:      x     = (const float*)d_in[i]; break;
            case 2 * NE:      ei    = (const int*)d_in[i];   break;
            case NN:          batch = (const int*)d_in[i];   break;
            case NL * D * D:  W     = (const float*)d_in[i]; break;
            case NL * D:      b     = (const float*)d_in[i]; break;
            case D:           lin_w = (const float*)d_in[i]; break;
            case 1:           lin_b = (const float*)d_in[i]; break;
        }
    }
    float* out = (float*)d_out;

    // one-time host resources (created on the correctness call, pre-capture)
    static cudaStream_t side = 0;
    static cudaEvent_t evF = 0, evJ = 0;
    if (!side) {
        cudaStreamCreateWithFlags(&side, cudaStreamNonBlocking);
        cudaEventCreateWithFlags(&evF, cudaEventDisableTiming);
        cudaEventCreateWithFlags(&evJ, cudaEventDisableTiming);
    }

    const int T = 256;

    // fork: prep chain on side stream, concurrent with wprep + gemm0
    cudaEventRecord(evF, 0);
    cudaStreamWaitEvent(side, evF, 0);

    k_init <<<(NN + T - 1) / T, T, 0, side>>>();
    k_deg  <<<(NE + T - 1) / T, T, 0, side>>>(ei);
    k_scanA<<<SCAN_NBLK, 1024, 0, side>>>();
    k_scanB<<<1, 32, 0, side>>>();
    k_scanC<<<SCAN_NBLK, 1024, 0, side>>>();
    k_fill <<<(NE + T - 1) / T, T, 0, side>>>(ei);
    k_bnd  <<<(NN + T - 1) / T, T, 0, side>>>(batch);

    int gemmGrid   = (NN + 127) / 128;
    int gatherGrid = (NN * 32 + T - 1) / T;

    k_wprep<<<(NL * 16 * 16 * 32 + T - 1) / T, T>>>(W);
    k_gemm <<<gemmGrid, T>>>(x, b, 0);

    // join: gather0 needs fill (side) + gemm0 (main)
    cudaEventRecord(evJ, side);
    cudaStreamWaitEvent(0, evJ, 0);

    k_gather<<<gatherGrid, T>>>();
    k_gemm  <<<gemmGrid, T>>>(x, b + 0 * D, 1);
    k_gather<<<gatherGrid, T>>>();
    k_gemm  <<<gemmGrid, T>>>(x, b + 1 * D, 2);
    k_gather<<<gatherGrid, T>>>();

    k_poolout<<<NG, 128>>>(b + 2 * D, lin_w, lin_b, out);
}

// round 9
// speedup vs baseline: 1.6295x; 1.0919x over previous
#include <cuda_runtime.h>
#include <cuda_fp16.h>
#include <cstdint>

#define NN 100000
#define NE 1600000
#define D  128
#define NG 2048
#define NL 3
#define SCAN_NBLK ((NN + 1023) / 1024)   // 98

// ---------------- scratch (device globals: alloc-free) ----------------
__device__ int      g_degi [NN];
__device__ float    g_dinv [NN];
__device__ int      g_fill [NN];
__device__ int      g_off  [NN + 1];
__device__ int      g_part [SCAN_NBLK];
__device__ int      g_csrc [NE];
__device__ float    g_cnrm [NE];
__device__ int      g_start[NG + 1];
__device__ __align__(8) __half g_th [NN * D];   // t = h @ W, fp16
__device__ float    g_agg  [NN * D];
// W in tf32, fragment-ordered: [layer][kstep 16][ntile 16][lane 32][2]
__device__ uint32_t g_wf   [NL * 16 * 16 * 64];

__device__ __forceinline__ void fma4(float4& a, float s, const float4& c) {
    a.x = fmaf(s, c.x, a.x);
    a.y = fmaf(s, c.y, a.y);
    a.z = fmaf(s, c.z, a.z);
    a.w = fmaf(s, c.w, a.w);
}

// load 4 halves (8B) and widen to float4
__device__ __forceinline__ float4 ldt4(const uint2* t2, long idx) {
    uint2 r = __ldg(&t2[idx]);
    __half2 h0 = *(__half2*)&r.x;
    __half2 h1 = *(__half2*)&r.y;
    float2 f0 = __half22float2(h0);
    float2 f1 = __half22float2(h1);
    return make_float4(f0.x, f0.y, f1.x, f1.y);
}

__device__ __forceinline__ uint32_t f2tf32(float f) {
    uint32_t r;
    asm("cvt.rna.tf32.f32 %0, %1;" : "=r"(r) : "f"(f));
    return r;
}

// ---------------- init ------------------------------------------------
__global__ void k_init() {
    int i = blockIdx.x * blockDim.x + threadIdx.x;
    if (i < NN) { g_degi[i] = 1; g_fill[i] = 0; }
}

__global__ void k_deg(const int* __restrict__ ei) {
    int e = blockIdx.x * blockDim.x + threadIdx.x;
    if (e < NE) atomicAdd(&g_degi[ei[NE + e]], 1);
}

// ---------------- 3-pass exclusive scan of (deg-1) ---------------------
__global__ void __launch_bounds__(1024)
k_scanA() {
    __shared__ int wsum[32];
    int tid = threadIdx.x, lane = tid & 31, w = tid >> 5;
    int i = blockIdx.x * 1024 + tid;
    int s = (i < NN) ? (g_degi[i] - 1) : 0;
    #pragma unroll
    for (int o = 16; o > 0; o >>= 1) s += __shfl_xor_sync(0xffffffffu, s, o);
    if (lane == 0) wsum[w] = s;
    __syncthreads();
    if (w == 0) {
        int t = wsum[lane];
        #pragma unroll
        for (int o = 16; o > 0; o >>= 1) t += __shfl_xor_sync(0xffffffffu, t, o);
        if (lane == 0) g_part[blockIdx.x] = t;
    }
}

__global__ void k_scanB() {
    int lane = threadIdx.x;
    int carry = 0;
    for (int base = 0; base < SCAN_NBLK; base += 32) {
        int i = base + lane;
        int v = (i < SCAN_NBLK) ? g_part[i] : 0;
        int incl = v;
        #pragma unroll
        for (int o = 1; o < 32; o <<= 1) {
            int t = __shfl_up_sync(0xffffffffu, incl, o);
            if (lane >= o) incl += t;
        }
        if (i < SCAN_NBLK) g_part[i] = carry + incl - v;
        carry += __shfl_sync(0xffffffffu, incl, 31);
    }
}

__global__ void __launch_bounds__(1024)
k_scanC() {
    __shared__ int wsum[32];
    int tid = threadIdx.x, lane = tid & 31, w = tid >> 5;
    int i = blockIdx.x * 1024 + tid;
    int val = (i < NN) ? (g_degi[i] - 1) : 0;
    int incl = val;
    #pragma unroll
    for (int o = 1; o < 32; o <<= 1) {
        int t = __shfl_up_sync(0xffffffffu, incl, o);
        if (lane >= o) incl += t;
    }
    if (lane == 31) wsum[w] = incl;
    __syncthreads();
    if (w == 0) {
        int s = wsum[lane];
        #pragma unroll
        for (int o = 1; o < 32; o <<= 1) {
            int t = __shfl_up_sync(0xffffffffu, s, o);
            if (lane >= o) s += t;
        }
        wsum[lane] = s;
    }
    __syncthreads();
    if (i < NN) {
        g_off[i] = g_part[blockIdx.x] + (w ? wsum[w - 1] : 0) + incl - val;
        g_dinv[i] = rsqrtf((float)g_degi[i]);
    }
    if (i == 0) g_off[NN] = NE;
}

// ---------------- CSR fill ---------------------------------------------
__global__ void k_fill(const int* __restrict__ ei) {
    int e = blockIdx.x * blockDim.x + threadIdx.x;
    if (e >= NE) return;
    int s = ei[e];
    int d = ei[NE + e];
    int pos = g_off[d] + atomicAdd(&g_fill[d], 1);
    g_csrc[pos] = s;
    g_cnrm[pos] = g_dinv[s] * g_dinv[d];
}

// ---------------- graph boundaries --------------------------------------
__global__ void k_bnd(const int* __restrict__ batch) {
    int i = blockIdx.x * blockDim.x + threadIdx.x;
    if (i >= NN) return;
    int b1 = batch[i];
    int b0 = (i == 0) ? -1 : batch[i - 1];
    for (int g = b0 + 1; g <= b1; g++) g_start[g] = i;
    if (i == NN - 1)
        for (int g = b1 + 1; g <= NG; g++) g_start[g] = NN;
}

// ---------------- W -> tf32 fragment layout ------------------------------
__global__ void k_wprep(const float* __restrict__ W) {
    int tid = blockIdx.x * blockDim.x + threadIdx.x;    // 0 .. 24575
    if (tid >= NL * 16 * 16 * 32) return;
    int lane = tid & 31;
    int j    = (tid >> 5) & 15;
    int s    = (tid >> 9) & 15;
    int l    = tid >> 13;
    int g = lane >> 2, t = lane & 3;
    const float* Wl = W + l * D * D;
    float w0 = Wl[(8 * s + t) * D + 8 * j + g];
    float w1 = Wl[(8 * s + t + 4) * D + 8 * j + g];
    g_wf[tid * 2 + 0] = f2tf32(w0);
    g_wf[tid * 2 + 1] = f2tf32(w1);
}

// ---------------- TF32 tensor-core GEMM: t = prologue(in) @ W[l] --------
// Block 256 thr = 8 warps; warp w owns rows [blk*128 + 16w, +16), all N=128.
// Epilogue writes t in fp16 (halves gather L2 traffic).
__global__ void __launch_bounds__(256)
k_gemm(const float* __restrict__ x0, const float* __restrict__ bias, int layer) {
    const float* in = (layer == 0) ? x0 : g_agg;
    int lane = threadIdx.x & 31;
    int w    = threadIdx.x >> 5;
    int g = lane >> 2, t = lane & 3;
    int m0 = blockIdx.x * 128 + w * 16;
    int row0 = m0 + g;
    int row1 = m0 + g + 8;
    int r0c = (row0 < NN) ? row0 : (NN - 1);
    int r1c = (row1 < NN) ? row1 : (NN - 1);

    float acc[16][4];
    #pragma unroll
    for (int j = 0; j < 16; j++)
        { acc[j][0] = 0.f; acc[j][1] = 0.f; acc[j][2] = 0.f; acc[j][3] = 0.f; }

    const uint32_t* wf = g_wf + (layer * 16) * 16 * 64 + lane * 2;

    #pragma unroll
    for (int s = 0; s < 16; s++) {
        int k0 = 8 * s;
        float a0f = __ldg(&in[r0c * D + k0 + t]);
        float a1f = __ldg(&in[r1c * D + k0 + t]);
        float a2f = __ldg(&in[r0c * D + k0 + t + 4]);
        float a3f = __ldg(&in[r1c * D + k0 + t + 4]);
        if (layer != 0) {
            float b0 = __ldg(&bias[k0 + t]);
            float b1 = __ldg(&bias[k0 + t + 4]);
            a0f = fmaxf(a0f + b0, 0.f);
            a1f = fmaxf(a1f + b0, 0.f);
            a2f = fmaxf(a2f + b1, 0.f);
            a3f = fmaxf(a3f + b1, 0.f);
        }
        uint32_t a0 = f2tf32(a0f), a1 = f2tf32(a1f);
        uint32_t a2 = f2tf32(a2f), a3 = f2tf32(a3f);

        const uint32_t* wfs = wf + s * 16 * 64;
        #pragma unroll
        for (int j = 0; j < 16; j++) {
            uint2 bv = *(const uint2*)(wfs + j * 64);
            asm volatile(
                "mma.sync.aligned.m16n8k8.row.col.f32.tf32.tf32.f32 "
                "{%0,%1,%2,%3}, {%4,%5,%6,%7}, {%8,%9}, {%0,%1,%2,%3};"
                : "+f"(acc[j][0]), "+f"(acc[j][1]), "+f"(acc[j][2]), "+f"(acc[j][3])
                : "r"(a0), "r"(a1), "r"(a2), "r"(a3), "r"(bv.x), "r"(bv.y));
        }
    }

    __half2* th2 = (__half2*)g_th;
    #pragma unroll
    for (int j = 0; j < 16; j++) {
        int c = 8 * j + 2 * t;
        if (row0 < NN)
            th2[(row0 * D + c) >> 1] = __floats2half2_rn(acc[j][0], acc[j][1]);
        if (row1 < NN)
            th2[(row1 * D + c) >> 1] = __floats2half2_rn(acc[j][2], acc[j][3]);
    }
}

// ---------------- gather: agg[d] = dinv^2 * t[d] + sum norm * t[src] ----
// One warp per node; lane j owns 4 features (8B fp16). fp32 accumulation.
__global__ void __launch_bounds__(256)
k_gather() {
    int gw = (blockIdx.x * blockDim.x + threadIdx.x) >> 5;
    if (gw >= NN) return;
    int j = threadIdx.x & 31;
    int d = gw;
    const uint2* t2 = (const uint2*)g_th;   // 32 uint2 per row

    float dv = g_dinv[d];
    float s2 = dv * dv;
    float4 acc = ldt4(t2, (long)d * 32 + j);
    acc.x *= s2; acc.y *= s2; acc.z *= s2; acc.w *= s2;

    int e   = g_off[d];
    int end = g_off[d + 1];
    for (; e + 2 <= end; e += 2) {
        int   s0 = __ldg(&g_csrc[e]);
        int   s1 = __ldg(&g_csrc[e + 1]);
        float n0 = __ldg(&g_cnrm[e]);
        float n1 = __ldg(&g_cnrm[e + 1]);
        float4 v0 = ldt4(t2, (long)s0 * 32 + j);
        float4 v1 = ldt4(t2, (long)s1 * 32 + j);
        fma4(acc, n0, v0);
        fma4(acc, n1, v1);
    }
    if (e < end) {
        int   s0 = __ldg(&g_csrc[e]);
        float n0 = __ldg(&g_cnrm[e]);
        float4 v0 = ldt4(t2, (long)s0 * 32 + j);
        fma4(acc, n0, v0);
    }
    ((float4*)g_agg)[d * 32 + j] = acc;
}

// ---------------- fused pool + final linear ------------------------------
__global__ void __launch_bounds__(128)
k_poolout(const float* __restrict__ bias, const float* __restrict__ lin_w,
          const float* __restrict__ lin_b, float* __restrict__ out) {
    int g = blockIdx.x;
    int j = threadIdx.x;
    int beg = g_start[g];
    int end = g_start[g + 1];
    float bb = bias[j];
    float acc = 0.0f;
    for (int r = beg; r < end; r++)
        acc += fmaxf(g_agg[r * D + j] + bb, 0.0f);

    float p = acc * lin_w[j];
    #pragma unroll
    for (int o = 16; o > 0; o >>= 1) p += __shfl_xor_sync(0xffffffffu, p, o);

    __shared__ float ws[4];
    if ((j & 31) == 0) ws[j >> 5] = p;
    __syncthreads();
    if (j == 0) {
        float tot = ws[0] + ws[1] + ws[2] + ws[3];
        float cnt = (float)(end - beg);
        float inv = 1.0f / fmaxf(cnt, 1.0f);
        out[g] = tot * inv + lin_b[0];
    }
}

// ---------------- launch --------------------------------------------------
extern "C" void kernel_launch(void* const* d_in, const int* in_sizes, int n_in,
                              void* d_out, int out_size) {
    const float *x = 0, *W = 0, *b = 0, *lin_w = 0, *lin_b = 0;
    const int   *ei = 0, *batch = 0;
    for (int i = 0; i < n_in; i++) {
        switch (in_sizes[i]) {
            case NN * D:      x     = (const float*)d_in[i]; break;
            case 2 * NE:      ei    = (const int*)d_in[i];   break;
            case NN:          batch = (const int*)d_in[i];   break;
            case NL * D * D:  W     = (const float*)d_in[i]; break;
            case NL * D:      b     = (const float*)d_in[i]; break;
            case D:           lin_w = (const float*)d_in[i]; break;
            case 1:           lin_b = (const float*)d_in[i]; break;
        }
    }
    float* out = (float*)d_out;

    static cudaStream_t side = 0;
    static cudaEvent_t evF = 0, evJ = 0;
    if (!side) {
        cudaStreamCreateWithFlags(&side, cudaStreamNonBlocking);
        cudaEventCreateWithFlags(&evF, cudaEventDisableTiming);
        cudaEventCreateWithFlags(&evJ, cudaEventDisableTiming);
    }

    const int T = 256;

    // fork: prep chain on side stream, concurrent with wprep + gemm0
    cudaEventRecord(evF, 0);
    cudaStreamWaitEvent(side, evF, 0);

    k_init <<<(NN + T - 1) / T, T, 0, side>>>();
    k_deg  <<<(NE + T - 1) / T, T, 0, side>>>(ei);
    k_scanA<<<SCAN_NBLK, 1024, 0, side>>>();
    k_scanB<<<1, 32, 0, side>>>();
    k_scanC<<<SCAN_NBLK, 1024, 0, side>>>();
    k_fill <<<(NE + T - 1) / T, T, 0, side>>>(ei);
    k_bnd  <<<(NN + T - 1) / T, T, 0, side>>>(batch);

    int gemmGrid   = (NN + 127) / 128;
    int gatherGrid = (NN * 32 + T - 1) / T;

    k_wprep<<<(NL * 16 * 16 * 32 + T - 1) / T, T>>>(W);
    k_gemm <<<gemmGrid, T>>>(x, b, 0);

    // join: gather0 needs fill (side) + gemm0 (main)
    cudaEventRecord(evJ, side);
    cudaStreamWaitEvent(0, evJ, 0);

    k_gather<<<gatherGrid, T>>>();
    k_gemm  <<<gemmGrid, T>>>(x, b + 0 * D, 1);
    k_gather<<<gatherGrid, T>>>();
    k_gemm  <<<gemmGrid, T>>>(x, b + 1 * D, 2);
    k_gather<<<gatherGrid, T>>>();

    k_poolout<<<NG, 128>>>(b + 2 * D, lin_w, lin_b, out);
}